// round 3
// baseline (speedup 1.0000x reference)
#include <cuda_runtime.h>
#include <cstdint>
#include <cstddef>

#define NB 2
#define NT 2048
#define ND 1024
#define NH 16
#define NLAY 2
#define NE 8
#define NV 32000
#define NN (NB*NT)
#define NCAP 1024
#define NFF 4096

// ---------------- device scratch ----------------
__device__ float g_x   [(size_t)NN*ND];
__device__ float g_ln  [(size_t)NN*ND];
__device__ float g_qkv [(size_t)NN*3*ND];
__device__ float g_attn[(size_t)NN*ND];
__device__ float g_sc  [(size_t)NB*NH*NT*NT];
__device__ float g_route[NN*NE];
__device__ float g_noise[NN*NE];
__device__ float g_eps  [NN*NE];
__device__ float g_gate [NN*NE];
__device__ unsigned char g_mask[NN];
__device__ int   g_sel [NE*NCAP];
__device__ int   g_slot[NE*NN];
__device__ int   g_cnt [NE];
__device__ float g_xt  [(size_t)NE*NCAP*ND];
__device__ float g_h1  [(size_t)NE*NCAP*NFF];
__device__ float g_eo  [(size_t)NE*NCAP*ND];
__device__ float g_log [(size_t)NN*NV];
__device__ float g_nll [NN];
__device__ float g_vld [NN];

// ---------------- threefry2x32 (matches JAX) ----------------
__host__ __device__ __forceinline__ void threefry(unsigned k0, unsigned k1,
                                                  unsigned x0, unsigned x1,
                                                  unsigned& o0, unsigned& o1) {
    unsigned ks2 = k0 ^ k1 ^ 0x1BD11BDAu;
    x0 += k0; x1 += k1;
#define TFR(r) { x0 += x1; x1 = (x1 << (r)) | (x1 >> (32 - (r))); x1 ^= x0; }
    TFR(13) TFR(15) TFR(26) TFR(6)  x0 += k1;  x1 += ks2 + 1u;
    TFR(17) TFR(29) TFR(16) TFR(24) x0 += ks2; x1 += k0 + 2u;
    TFR(13) TFR(15) TFR(26) TFR(6)  x0 += k0;  x1 += k1 + 3u;
    TFR(17) TFR(29) TFR(16) TFR(24) x0 += k1;  x1 += ks2 + 4u;
    TFR(13) TFR(15) TFR(26) TFR(6)  x0 += ks2; x1 += k0 + 5u;
#undef TFR
    o0 = x0; o1 = x1;
}

// XLA ErfInv32 (Giles) polynomial
__device__ __forceinline__ float xla_erfinv(float x) {
    float w = -log1pf(-x * x);
    float p;
    if (w < 5.f) {
        w -= 2.5f;
        p = 2.81022636e-08f;
        p = fmaf(p, w, 3.43273939e-07f);
        p = fmaf(p, w, -3.5233877e-06f);
        p = fmaf(p, w, -4.39150654e-06f);
        p = fmaf(p, w, 0.00021858087f);
        p = fmaf(p, w, -0.00125372503f);
        p = fmaf(p, w, -0.00417768164f);
        p = fmaf(p, w, 0.246640727f);
        p = fmaf(p, w, 1.50140941f);
    } else {
        w = sqrtf(w) - 3.f;
        p = -0.000200214257f;
        p = fmaf(p, w, 0.000100950558f);
        p = fmaf(p, w, 0.00134934322f);
        p = fmaf(p, w, -0.00367342844f);
        p = fmaf(p, w, 0.00573950773f);
        p = fmaf(p, w, -0.0076224613f);
        p = fmaf(p, w, 0.00943887047f);
        p = fmaf(p, w, 1.00167406f);
        p = fmaf(p, w, 2.83297682f);
    }
    return p * x;
}

__device__ __forceinline__ float bits_to_normal(unsigned bits) {
    float f = __uint_as_float((bits >> 9) | 0x3F800000u) - 1.0f;  // [0,1)
    const float lo = -0.99999994f;                                // nextafter(-1,0)
    float u = fmaf(f, 2.0f, lo);                                  // hi-lo == 2.0f in fp32
    u = fmaxf(u, lo);
    return 1.41421356237f * xla_erfinv(u);
}

// ---------------- small kernels ----------------
__global__ void embed_kernel(const int* __restrict__ ids, const float* __restrict__ tok,
                             const float* __restrict__ pos, float* __restrict__ x) {
    int n = blockIdx.x, t = n % NT, id = ids[n];
    const float* te = tok + (size_t)id * ND;
    const float* pe = pos + (size_t)t * ND;
    float* dst = x + (size_t)n * ND;
    for (int d = threadIdx.x; d < ND; d += 256) dst[d] = te[d] + pe[d];
}

__global__ void ln_kernel(const float* __restrict__ x, const float* __restrict__ w,
                          const float* __restrict__ b, float* __restrict__ out) {
    int n = blockIdx.x, tid = threadIdx.x;
    const float* row = x + (size_t)n * ND;
    __shared__ float red[256];
    float s = 0.f;
    for (int d = tid; d < ND; d += 256) s += row[d];
    red[tid] = s; __syncthreads();
    for (int st = 128; st; st >>= 1) { if (tid < st) red[tid] += red[tid + st]; __syncthreads(); }
    float mu = red[0] * (1.0f / ND);
    __syncthreads();
    float v = 0.f;
    for (int d = tid; d < ND; d += 256) { float t = row[d] - mu; v += t * t; }
    red[tid] = v; __syncthreads();
    for (int st = 128; st; st >>= 1) { if (tid < st) red[tid] += red[tid + st]; __syncthreads(); }
    float rs = rsqrtf(red[0] * (1.0f / ND) + 1e-5f);
    float* dst = out + (size_t)n * ND;
    for (int d = tid; d < ND; d += 256) dst[d] = (row[d] - mu) * rs * w[d] + b[d];
}

__global__ void rope_kernel(float* __restrict__ qkv) {
    int nh = blockIdx.x;
    int n = nh >> 4, h = nh & 15;
    int t = n % NT, i = threadIdx.x;  // 0..31
    float ang = (float)t * expf((float)(2 * i) * (-0.14391156831212806f)); // -ln(1e4)/64
    float s = sinf(ang), c = cosf(ang);
    float* q = qkv + (size_t)n * 3072 + h * 64;
    float* k = q + 1024;
    float q1 = q[i], q2 = q[i + 32];
    q[i] = q1 * c - q2 * s; q[i + 32] = q2 * c + q1 * s;
    float k1 = k[i], k2 = k[i + 32];
    k[i] = k1 * c - k2 * s; k[i + 32] = k2 * c + k1 * s;
}

// ---------------- 64x64x16 SGEMM core ----------------
__device__ __forceinline__ void tile_fma(const float (*As)[68], const float (*Bs)[68],
                                         float acc[4][4], int ty4, int tx4) {
#pragma unroll
    for (int k = 0; k < 16; k++) {
        float a0 = As[k][ty4], a1 = As[k][ty4+1], a2 = As[k][ty4+2], a3 = As[k][ty4+3];
        float b0 = Bs[k][tx4], b1 = Bs[k][tx4+1], b2 = Bs[k][tx4+2], b3 = Bs[k][tx4+3];
        acc[0][0] += a0*b0; acc[0][1] += a0*b1; acc[0][2] += a0*b2; acc[0][3] += a0*b3;
        acc[1][0] += a1*b0; acc[1][1] += a1*b1; acc[1][2] += a1*b2; acc[1][3] += a1*b3;
        acc[2][0] += a2*b0; acc[2][1] += a2*b1; acc[2][2] += a2*b2; acc[2][3] += a2*b3;
        acc[3][0] += a3*b0; acc[3][1] += a3*b1; acc[3][2] += a3*b2; acc[3][3] += a3*b3;
    }
}

template<bool TRANSB, bool BIAS, bool RELU, bool ACCUM>
__global__ void sgemm_kernel(const float* __restrict__ A, const float* __restrict__ Bm,
                             const float* __restrict__ bias, float* __restrict__ C,
                             int M, int Nn, int Kd,
                             size_t sA, size_t sB, size_t sBias, size_t sC) {
    A += (size_t)blockIdx.z * sA;
    Bm += (size_t)blockIdx.z * sB;
    C += (size_t)blockIdx.z * sC;
    if (BIAS) bias += (size_t)blockIdx.z * sBias;
    const int m0 = blockIdx.y * 64, n0 = blockIdx.x * 64;
    __shared__ float As[16][68];
    __shared__ float Bs[16][68];
    const int tid = threadIdx.x;
    const int tx4 = (tid & 15) << 2, ty4 = (tid >> 4) << 2;
    float acc[4][4] = {};
    for (int k0 = 0; k0 < Kd; k0 += 16) {
        {   // A: M x Kd, tile 64x16 -> As[k][m]
            int row = tid >> 2, col = (tid & 3) << 2;
            float4 v = *(const float4*)(A + (size_t)(m0 + row) * Kd + k0 + col);
            As[col][row] = v.x; As[col+1][row] = v.y; As[col+2][row] = v.z; As[col+3][row] = v.w;
        }
        if (!TRANSB) {  // B: Kd x Nn
            int row = tid >> 4, col = (tid & 15) << 2;
            float4 v = *(const float4*)(Bm + (size_t)(k0 + row) * Nn + n0 + col);
            Bs[row][col] = v.x; Bs[row][col+1] = v.y; Bs[row][col+2] = v.z; Bs[row][col+3] = v.w;
        } else {        // B: Nn x Kd -> Bs[k][n]
            int nrow = tid >> 2, kcol = (tid & 3) << 2;
            float4 v = *(const float4*)(Bm + (size_t)(n0 + nrow) * Kd + k0 + kcol);
            Bs[kcol][nrow] = v.x; Bs[kcol+1][nrow] = v.y; Bs[kcol+2][nrow] = v.z; Bs[kcol+3][nrow] = v.w;
        }
        __syncthreads();
        tile_fma(As, Bs, acc, ty4, tx4);
        __syncthreads();
    }
#pragma unroll
    for (int i = 0; i < 4; i++) {
        int gm = m0 + ty4 + i;
#pragma unroll
        for (int j = 0; j < 4; j++) {
            int gn = n0 + tx4 + j;
            float v = acc[i][j];
            if (BIAS) v += bias[gn];
            if (RELU) v = fmaxf(v, 0.f);
            if (ACCUM) C[(size_t)gm * Nn + gn] += v;
            else       C[(size_t)gm * Nn + gn] = v;
        }
    }
}

// ---------------- attention ----------------
__global__ void attn_qk_kernel(const float* __restrict__ qkv, float* __restrict__ sc) {
    int ct = blockIdx.x, qt = blockIdx.y, z = blockIdx.z;
    if (ct > qt) return;
    int b = z >> 4, h = z & 15;
    const float* Qb = qkv + (size_t)b * NT * 3072 + (size_t)h * 64;
    const float* Kb = Qb + 1024;
    float* Cb = sc + (size_t)z * NT * NT;
    __shared__ float As[16][68];
    __shared__ float Bs[16][68];
    int tid = threadIdx.x;
    int tx4 = (tid & 15) << 2, ty4 = (tid >> 4) << 2;
    float acc[4][4] = {};
    for (int k0 = 0; k0 < 64; k0 += 16) {
        int row = tid >> 2, col = (tid & 3) << 2;
        float4 v = *(const float4*)(Qb + (size_t)(qt * 64 + row) * 3072 + k0 + col);
        As[col][row] = v.x; As[col+1][row] = v.y; As[col+2][row] = v.z; As[col+3][row] = v.w;
        float4 w = *(const float4*)(Kb + (size_t)(ct * 64 + row) * 3072 + k0 + col);
        Bs[col][row] = w.x; Bs[col+1][row] = w.y; Bs[col+2][row] = w.z; Bs[col+3][row] = w.w;
        __syncthreads();
        tile_fma(As, Bs, acc, ty4, tx4);
        __syncthreads();
    }
#pragma unroll
    for (int i = 0; i < 4; i++)
#pragma unroll
        for (int j = 0; j < 4; j++)
            Cb[(size_t)(qt * 64 + ty4 + i) * NT + ct * 64 + tx4 + j] = acc[i][j] * 0.125f;
}

__global__ void attn_softmax_kernel(float* __restrict__ sc) {
    int r = blockIdx.x, tid = threadIdx.x;
    float* row = sc + (size_t)blockIdx.y * NT * NT + (size_t)r * NT;
    int n = r + 1;
    __shared__ float red[128];
    float m = -3.4e38f;
    for (int j = tid; j < n; j += 128) m = fmaxf(m, row[j]);
    red[tid] = m; __syncthreads();
    for (int s = 64; s; s >>= 1) { if (tid < s) red[tid] = fmaxf(red[tid], red[tid + s]); __syncthreads(); }
    m = red[0]; __syncthreads();
    float sum = 0.f;
    for (int j = tid; j < n; j += 128) { float e = expf(row[j] - m); row[j] = e; sum += e; }
    red[tid] = sum; __syncthreads();
    for (int s = 64; s; s >>= 1) { if (tid < s) red[tid] += red[tid + s]; __syncthreads(); }
    float inv = 1.0f / red[0];
    for (int j = tid; j < n; j += 128) row[j] *= inv;
    int rup = ((r >> 6) + 1) << 6;
    for (int j = n + tid; j < rup; j += 128) row[j] = 0.f;
}

__global__ void attn_pv_kernel(const float* __restrict__ sc, const float* __restrict__ qkv,
                               float* __restrict__ attn) {
    int qt = blockIdx.y, z = blockIdx.z;
    int b = z >> 4, h = z & 15;
    const float* Pb = sc + (size_t)z * NT * NT;
    const float* Vb = qkv + (size_t)b * NT * 3072 + 2048 + (size_t)h * 64;
    float* Ob = attn + (size_t)b * NT * 1024 + (size_t)h * 64;
    __shared__ float As[16][68];
    __shared__ float Bs[16][68];
    int tid = threadIdx.x;
    int tx4 = (tid & 15) << 2, ty4 = (tid >> 4) << 2;
    float acc[4][4] = {};
    int kend = (qt + 1) * 64;
    for (int k0 = 0; k0 < kend; k0 += 16) {
        {
            int row = tid >> 2, col = (tid & 3) << 2;
            float4 v = *(const float4*)(Pb + (size_t)(qt * 64 + row) * NT + k0 + col);
            As[col][row] = v.x; As[col+1][row] = v.y; As[col+2][row] = v.z; As[col+3][row] = v.w;
        }
        {
            int row = tid >> 4, col = (tid & 15) << 2;
            float4 v = *(const float4*)(Vb + (size_t)(k0 + row) * 3072 + col);
            Bs[row][col] = v.x; Bs[row][col+1] = v.y; Bs[row][col+2] = v.z; Bs[row][col+3] = v.w;
        }
        __syncthreads();
        tile_fma(As, Bs, acc, ty4, tx4);
        __syncthreads();
    }
#pragma unroll
    for (int i = 0; i < 4; i++)
#pragma unroll
        for (int j = 0; j < 4; j++)
            Ob[(size_t)(qt * 64 + ty4 + i) * 1024 + tx4 + j] = acc[i][j];
}

// ---------------- MoE ----------------
__global__ void route_kernel(const float* __restrict__ ln, const float* __restrict__ wr,
                             const float* __restrict__ br, const float* __restrict__ wn,
                             const float* __restrict__ bn, float* __restrict__ route,
                             float* __restrict__ noise) {
    int n = blockIdx.x, tid = threadIdx.x;
    __shared__ float xs[ND];
    for (int d = tid; d < ND; d += 256) xs[d] = ln[(size_t)n * ND + d];
    __syncthreads();
    int w = tid >> 5, lane = tid & 31;
    float sr = 0.f, sn = 0.f;
    for (int d = lane; d < ND; d += 32) {
        float xv = xs[d];
        sr += xv * wr[(size_t)d * NE + w];
        sn += xv * wn[(size_t)d * NE + w];
    }
    for (int o = 16; o; o >>= 1) { sr += __shfl_down_sync(~0u, sr, o); sn += __shfl_down_sync(~0u, sn, o); }
    if (!lane) { route[n * NE + w] = sr + br[w]; noise[n * NE + w] = sn + bn[w]; }
}

// JAX partitionable threefry bits: out[i] = o0 ^ o1, counter = (hi=0, lo=i)
__global__ void eps_kernel(unsigned k0, unsigned k1, float* __restrict__ eps) {
    int i = blockIdx.x * 256 + threadIdx.x;
    if (i >= NN * NE) return;
    unsigned o0, o1;
    threefry(k0, k1, 0u, (unsigned)i, o0, o1);
    eps[i] = bits_to_normal(o0 ^ o1);
}

__global__ void topk_kernel(const float* __restrict__ route, const float* __restrict__ noise,
                            const float* __restrict__ eps, float* __restrict__ gate,
                            unsigned char* __restrict__ mask) {
    int n = blockIdx.x * 256 + threadIdx.x;
    if (n >= NN) return;
    float nv[NE];
#pragma unroll
    for (int e = 0; e < NE; e++) {
        float x = noise[n * NE + e];
        float sp = fmaxf(x, 0.f) + log1pf(expf(-fabsf(x)));
        nv[e] = route[n * NE + e] + eps[n * NE + e] * sp;
    }
    int i1 = 0; float v1 = nv[0];
#pragma unroll
    for (int e = 1; e < NE; e++) if (nv[e] > v1) { v1 = nv[e]; i1 = e; }
    int i2 = -1; float v2 = -3.4e38f;
#pragma unroll
    for (int e = 0; e < NE; e++) if (e != i1 && nv[e] > v2) { v2 = nv[e]; i2 = e; }
    float e2 = expf(v2 - v1);
    float Z = 1.0f + e2;
#pragma unroll
    for (int e = 0; e < NE; e++)
        gate[n * NE + e] = (e == i1) ? (1.0f / Z) : ((e == i2) ? (e2 / Z) : 0.f);
    mask[n] = (unsigned char)((1u << i1) | (1u << i2));
}

__global__ void select_kernel(const unsigned char* __restrict__ mask, int* __restrict__ sel,
                              int* __restrict__ slot, int* __restrict__ cnt) {
    int e = blockIdx.x, lane = threadIdx.x;
    int base = 0;
    for (int n0 = 0; n0 < NN; n0 += 32) {
        int n = n0 + lane;
        bool f = (mask[n] >> e) & 1;
        unsigned bal = __ballot_sync(0xffffffffu, f);
        int pos = base + __popc(bal & ((1u << lane) - 1u));
        int sl = (f && pos < NCAP) ? pos : -1;
        slot[(size_t)e * NN + n] = sl;
        if (sl >= 0) sel[e * NCAP + sl] = n;
        base += __popc(bal);
    }
    if (!lane) cnt[e] = base < NCAP ? base : NCAP;
}

__global__ void gather_kernel(const float* __restrict__ ln, const int* __restrict__ sel,
                              const int* __restrict__ cnt, float* __restrict__ xt) {
    int s = blockIdx.x;
    int e = s / NCAP, i = s % NCAP;
    float* dst = xt + (size_t)s * ND;
    if (i < cnt[e]) {
        const float* src = ln + (size_t)sel[s] * ND;
        for (int d = threadIdx.x; d < ND; d += 256) dst[d] = src[d];
    } else {
        for (int d = threadIdx.x; d < ND; d += 256) dst[d] = 0.f;
    }
}

__global__ void moe_scatter_kernel(const float* __restrict__ eo, const int* __restrict__ slot,
                                   const float* __restrict__ gate, float* __restrict__ x) {
    int n = blockIdx.x, tid = threadIdx.x;
    __shared__ int ss[NE];
    __shared__ float gg[NE];
    if (tid < NE) { ss[tid] = slot[(size_t)tid * NN + n]; gg[tid] = gate[n * NE + tid]; }
    __syncthreads();
    for (int d = tid; d < ND; d += 256) {
        float acc = 0.f;
#pragma unroll
        for (int e = 0; e < NE; e++) {
            int s = ss[e];
            if (s >= 0) acc += gg[e] * eo[((size_t)e * NCAP + s) * ND + d];
        }
        x[(size_t)n * ND + d] += acc;
    }
}

// ---------------- loss ----------------
__global__ void loss_kernel(const float* __restrict__ logits, const int* __restrict__ ids,
                            float* __restrict__ nll, float* __restrict__ vld) {
    int n = blockIdx.x, tid = threadIdx.x;
    int b = n / NT, t = n % NT;
    if (t == NT - 1) { if (!tid) { nll[n] = 0.f; vld[n] = 0.f; } return; }
    int tgt = ids[b * NT + t + 1];
    const float* row = logits + (size_t)n * NV;
    float m = -3.4e38f, s = 0.f;
    for (int j = tid; j < NV; j += 256) {
        float l = row[j];
        if (l > m) { s = s * expf(m - l) + 1.0f; m = l; }
        else s += expf(l - m);
    }
    __shared__ float sm[256], ssum[256];
    sm[tid] = m; ssum[tid] = s; __syncthreads();
    for (int st = 128; st; st >>= 1) {
        if (tid < st) {
            float m1 = sm[tid], s1 = ssum[tid], m2 = sm[tid + st], s2 = ssum[tid + st];
            float M = fmaxf(m1, m2);
            ssum[tid] = s1 * expf(m1 - M) + s2 * expf(m2 - M);
            sm[tid] = M;
        }
        __syncthreads();
    }
    if (!tid) {
        float lse = sm[0] + logf(ssum[0]);
        float v = (tgt != 2) ? 1.f : 0.f;
        nll[n] = -(row[tgt] - lse) * v;
        vld[n] = v;
    }
}

__global__ void reduce_kernel(const float* __restrict__ nll, const float* __restrict__ vld,
                              float* __restrict__ out) {
    __shared__ float s1[256], s2[256];
    int tid = threadIdx.x;
    float a = 0.f, b = 0.f;
    for (int i = tid; i < NN; i += 256) { a += nll[i]; b += vld[i]; }
    s1[tid] = a; s2[tid] = b; __syncthreads();
    for (int st = 128; st; st >>= 1) { if (tid < st) { s1[tid] += s1[tid + st]; s2[tid] += s2[tid + st]; } __syncthreads(); }
    if (!tid) out[0] = s1[0] / fmaxf(s2[0], 1.0f);
}

// ---------------- host launch ----------------
extern "C" void kernel_launch(void* const* d_in, const int* in_sizes, int n_in,
                              void* d_out, int out_size) {
    const int*   ids     = (const int*)d_in[0];
    const float* tok_emb = (const float*)d_in[1];
    const float* pos_emb = (const float*)d_in[2];
    const float* ln1_w   = (const float*)d_in[3];
    const float* ln1_b   = (const float*)d_in[4];
    const float* ln2_w   = (const float*)d_in[5];
    const float* ln2_b   = (const float*)d_in[6];
    const float* w_qkv   = (const float*)d_in[7];
    const float* w_out   = (const float*)d_in[8];
    const float* w_route = (const float*)d_in[9];
    const float* b_route = (const float*)d_in[10];
    const float* w_noise = (const float*)d_in[11];
    const float* b_noise = (const float*)d_in[12];
    const float* w_e1    = (const float*)d_in[13];
    const float* b_e1    = (const float*)d_in[14];
    const float* w_e2    = (const float*)d_in[15];
    const float* b_e2    = (const float*)d_in[16];
    const float* lnf_w   = (const float*)d_in[17];
    const float* lnf_b   = (const float*)d_in[18];
    float* out = (float*)d_out;

    float *x, *ln, *qkv, *attn, *sc, *route, *noise, *eps, *gate, *xt, *h1, *eo, *lg, *nll, *vld;
    unsigned char* mask; int *sel, *slot, *cnt;
    cudaGetSymbolAddress((void**)&x, g_x);       cudaGetSymbolAddress((void**)&ln, g_ln);
    cudaGetSymbolAddress((void**)&qkv, g_qkv);   cudaGetSymbolAddress((void**)&attn, g_attn);
    cudaGetSymbolAddress((void**)&sc, g_sc);     cudaGetSymbolAddress((void**)&route, g_route);
    cudaGetSymbolAddress((void**)&noise, g_noise); cudaGetSymbolAddress((void**)&eps, g_eps);
    cudaGetSymbolAddress((void**)&gate, g_gate); cudaGetSymbolAddress((void**)&mask, g_mask);
    cudaGetSymbolAddress((void**)&sel, g_sel);   cudaGetSymbolAddress((void**)&slot, g_slot);
    cudaGetSymbolAddress((void**)&cnt, g_cnt);   cudaGetSymbolAddress((void**)&xt, g_xt);
    cudaGetSymbolAddress((void**)&h1, g_h1);     cudaGetSymbolAddress((void**)&eo, g_eo);
    cudaGetSymbolAddress((void**)&lg, g_log);    cudaGetSymbolAddress((void**)&nll, g_nll);
    cudaGetSymbolAddress((void**)&vld, g_vld);

    embed_kernel<<<NN, 256>>>(ids, tok_emb, pos_emb, x);

    for (int l = 0; l < NLAY; l++) {
        // attention block
        ln_kernel<<<NN, 256>>>(x, ln1_w + l * ND, ln1_b + l * ND, ln);
        sgemm_kernel<false,false,false,false><<<dim3(3*ND/64, NN/64), 256>>>(
            ln, w_qkv + (size_t)l * ND * 3 * ND, nullptr, qkv, NN, 3*ND, ND, 0,0,0,0);
        rope_kernel<<<NN * NH, 32>>>(qkv);
        attn_qk_kernel<<<dim3(NT/64, NT/64, NB*NH), 256>>>(qkv, sc);
        attn_softmax_kernel<<<dim3(NT, NB*NH), 128>>>(sc);
        attn_pv_kernel<<<dim3(1, NT/64, NB*NH), 256>>>(sc, qkv, attn);
        sgemm_kernel<false,false,false,true><<<dim3(ND/64, NN/64), 256>>>(
            attn, w_out + (size_t)l * ND * ND, nullptr, x, NN, ND, ND, 0,0,0,0);

        // MoE block
        ln_kernel<<<NN, 256>>>(x, ln2_w + l * ND, ln2_b + l * ND, ln);
        route_kernel<<<NN, 256>>>(ln, w_route + (size_t)l * ND * NE, b_route + l * NE,
                                  w_noise + (size_t)l * ND * NE, b_noise + l * NE, route, noise);
        // per-layer key: fold_in(key(1234), l) = threefry([0,1234],[0,l])
        unsigned k0, k1;
        threefry(0u, 1234u, 0u, (unsigned)l, k0, k1);
        eps_kernel<<<(NN * NE + 255) / 256, 256>>>(k0, k1, eps);
        topk_kernel<<<(NN + 255) / 256, 256>>>(route, noise, eps, gate, mask);
        select_kernel<<<NE, 32>>>(mask, sel, slot, cnt);
        gather_kernel<<<NE * NCAP, 256>>>(ln, sel, cnt, xt);
        sgemm_kernel<false,true,true,false><<<dim3(NFF/64, NCAP/64, NE), 256>>>(
            xt, w_e1 + (size_t)l * NE * ND * NFF, b_e1 + (size_t)l * NE * NFF, h1,
            NCAP, NFF, ND, (size_t)NCAP*ND, (size_t)ND*NFF, NFF, (size_t)NCAP*NFF);
        sgemm_kernel<false,true,false,false><<<dim3(ND/64, NCAP/64, NE), 256>>>(
            h1, w_e2 + (size_t)l * NE * NFF * ND, b_e2 + (size_t)l * NE * ND, eo,
            NCAP, ND, NFF, (size_t)NCAP*NFF, (size_t)NFF*ND, ND, (size_t)NCAP*ND);
        moe_scatter_kernel<<<NN, 256>>>(eo, slot, gate, x);
    }

    ln_kernel<<<NN, 256>>>(x, lnf_w, lnf_b, ln);
    sgemm_kernel<true,false,false,false><<<dim3(NV/64, NN/64), 256>>>(
        ln, tok_emb, nullptr, lg, NN, NV, ND, 0,0,0,0);
    loss_kernel<<<NN, 256>>>(lg, ids, nll, vld);
    reduce_kernel<<<1, 256>>>(nll, vld, out);
}

// round 4
// speedup vs baseline: 2.1541x; 2.1541x over previous
#include <cuda_runtime.h>
#include <cstdint>
#include <cstddef>

#define NB 2
#define NT 2048
#define ND 1024
#define NH 16
#define NLAY 2
#define NE 8
#define NV 32000
#define NN (NB*NT)
#define NCAP 1024
#define NFF 4096

// ---------------- device scratch ----------------
__device__ float g_x   [(size_t)NN*ND];
__device__ float g_ln  [(size_t)NN*ND];
__device__ float g_qkv [(size_t)NN*3*ND];
__device__ float g_attn[(size_t)NN*ND];
__device__ float g_sc  [(size_t)NB*NH*NT*NT];
__device__ float g_route[NN*NE];
__device__ float g_noise[NN*NE];
__device__ float g_eps  [NN*NE];
__device__ float g_gate [NN*NE];
__device__ unsigned char g_mask[NN];
__device__ int   g_sel [NE*NCAP];
__device__ int   g_slot[NE*NN];
__device__ int   g_cnt [NE];
__device__ float g_xt  [(size_t)NE*NCAP*ND];
__device__ float g_h1  [(size_t)NE*NCAP*NFF];
__device__ float g_eo  [(size_t)NE*NCAP*ND];
__device__ float g_log [(size_t)NN*NV];
__device__ float g_nll [NN];
__device__ float g_vld [NN];

// ---------------- threefry2x32 (matches JAX) ----------------
__host__ __device__ __forceinline__ void threefry(unsigned k0, unsigned k1,
                                                  unsigned x0, unsigned x1,
                                                  unsigned& o0, unsigned& o1) {
    unsigned ks2 = k0 ^ k1 ^ 0x1BD11BDAu;
    x0 += k0; x1 += k1;
#define TFR(r) { x0 += x1; x1 = (x1 << (r)) | (x1 >> (32 - (r))); x1 ^= x0; }
    TFR(13) TFR(15) TFR(26) TFR(6)  x0 += k1;  x1 += ks2 + 1u;
    TFR(17) TFR(29) TFR(16) TFR(24) x0 += ks2; x1 += k0 + 2u;
    TFR(13) TFR(15) TFR(26) TFR(6)  x0 += k0;  x1 += k1 + 3u;
    TFR(17) TFR(29) TFR(16) TFR(24) x0 += k1;  x1 += ks2 + 4u;
    TFR(13) TFR(15) TFR(26) TFR(6)  x0 += ks2; x1 += k0 + 5u;
#undef TFR
    o0 = x0; o1 = x1;
}

// XLA ErfInv32 (Giles) polynomial
__device__ __forceinline__ float xla_erfinv(float x) {
    float w = -log1pf(-x * x);
    float p;
    if (w < 5.f) {
        w -= 2.5f;
        p = 2.81022636e-08f;
        p = fmaf(p, w, 3.43273939e-07f);
        p = fmaf(p, w, -3.5233877e-06f);
        p = fmaf(p, w, -4.39150654e-06f);
        p = fmaf(p, w, 0.00021858087f);
        p = fmaf(p, w, -0.00125372503f);
        p = fmaf(p, w, -0.00417768164f);
        p = fmaf(p, w, 0.246640727f);
        p = fmaf(p, w, 1.50140941f);
    } else {
        w = sqrtf(w) - 3.f;
        p = -0.000200214257f;
        p = fmaf(p, w, 0.000100950558f);
        p = fmaf(p, w, 0.00134934322f);
        p = fmaf(p, w, -0.00367342844f);
        p = fmaf(p, w, 0.00573950773f);
        p = fmaf(p, w, -0.0076224613f);
        p = fmaf(p, w, 0.00943887047f);
        p = fmaf(p, w, 1.00167406f);
        p = fmaf(p, w, 2.83297682f);
    }
    return p * x;
}

__device__ __forceinline__ float bits_to_normal(unsigned bits) {
    float f = __uint_as_float((bits >> 9) | 0x3F800000u) - 1.0f;
    const float lo = -0.99999994f;
    float u = fmaf(f, 2.0f, lo);
    u = fmaxf(u, lo);
    return 1.41421356237f * xla_erfinv(u);
}

// ---------------- tf32 mma helpers ----------------
__device__ __forceinline__ unsigned f2tf(float f) {
    unsigned u; asm("cvt.rna.tf32.f32 %0, %1;" : "=r"(u) : "f"(f)); return u;
}

__device__ __forceinline__ void mma_tf32(float* c, const unsigned* a, const unsigned* b) {
    asm volatile("mma.sync.aligned.m16n8k8.row.col.f32.tf32.tf32.f32 "
        "{%0,%1,%2,%3}, {%4,%5,%6,%7}, {%8,%9}, {%0,%1,%2,%3};"
        : "+f"(c[0]), "+f"(c[1]), "+f"(c[2]), "+f"(c[3])
        : "r"(a[0]), "r"(a[1]), "r"(a[2]), "r"(a[3]), "r"(b[0]), "r"(b[1]));
}

// ---------------- universal tf32 tensor-core GEMM ----------------
// C[M,N] = A[M,K] (row-major, lda) * B (BNK? [N,K] : [K,N], ldb)
// CAUSAL: skip blocks with n0 > m0 (square tiles). PVLIM: Keff = (by+1)*BM.
template<int BM, int BN, int WR, int WC, bool BNK, bool BIAS, bool RELU,
         bool ACCUM, bool CAUSAL, bool PVLIM>
__global__ void __launch_bounds__(256)
tc_gemm(const float* __restrict__ A, const float* __restrict__ B,
        const float* __restrict__ bias, float* __restrict__ C,
        int K, int lda, int ldb, int ldc, int zdiv,
        size_t sA, size_t sA2, size_t sB, size_t sB2,
        size_t sC, size_t sC2, size_t sBias, float scale)
{
    constexpr int BK = 16;
    constexpr int WM = BM / WR, WN = BN / WC;
    constexpr int MT = WM / 16, NT4 = WN / 8;
    constexpr int ANV = (BM * BK) / (4 * 256);
    constexpr int BNV = (BN * BK) / (4 * 256);

    const int m0 = blockIdx.y * BM, n0 = blockIdx.x * BN;
    if (CAUSAL && n0 > m0) return;

    const int tid = threadIdx.x, lane = tid & 31, warp = tid >> 5;
    const int wr = warp / WC, wc = warp % WC;
    const int g = lane >> 2, t = lane & 3;

    {
        int z = blockIdx.z, z1 = z / zdiv, z0 = z - z1 * zdiv;
        A += (size_t)z1 * sA + (size_t)z0 * sA2;
        B += (size_t)z1 * sB + (size_t)z0 * sB2;
        C += (size_t)z1 * sC + (size_t)z0 * sC2;
        if (BIAS) bias += (size_t)z1 * sBias;
    }

    int Keff = K;
    if (PVLIM) { int ke = ((int)blockIdx.y + 1) * BM; if (ke < Keff) Keff = ke; }
    const int nk = Keff / BK;

    __shared__ unsigned As[2][BM][20];
    __shared__ unsigned Bs[2][BN][20];

    float4 pa[ANV], pb[BNV];

    auto gload = [&](int k0) {
#pragma unroll
        for (int i = 0; i < ANV; i++) {
            int idx = tid + i * 256;
            int m = idx >> 2, c4 = (idx & 3) << 2;
            pa[i] = *(const float4*)(A + (size_t)(m0 + m) * lda + k0 + c4);
        }
        if (BNK) {
#pragma unroll
            for (int i = 0; i < BNV; i++) {
                int idx = tid + i * 256;
                int n = idx >> 2, c4 = (idx & 3) << 2;
                pb[i] = *(const float4*)(B + (size_t)(n0 + n) * ldb + k0 + c4);
            }
        } else {
#pragma unroll
            for (int i = 0; i < BNV; i++) {
                int idx = tid + i * 256;
                int kk = idx / (BN / 4), c4 = (idx % (BN / 4)) << 2;
                pb[i] = *(const float4*)(B + (size_t)(k0 + kk) * ldb + n0 + c4);
            }
        }
    };
    auto sstore = [&](int buf) {
#pragma unroll
        for (int i = 0; i < ANV; i++) {
            int idx = tid + i * 256;
            int m = idx >> 2, c4 = (idx & 3) << 2;
            As[buf][m][c4 + 0] = f2tf(pa[i].x);
            As[buf][m][c4 + 1] = f2tf(pa[i].y);
            As[buf][m][c4 + 2] = f2tf(pa[i].z);
            As[buf][m][c4 + 3] = f2tf(pa[i].w);
        }
        if (BNK) {
#pragma unroll
            for (int i = 0; i < BNV; i++) {
                int idx = tid + i * 256;
                int n = idx >> 2, c4 = (idx & 3) << 2;
                Bs[buf][n][c4 + 0] = f2tf(pb[i].x);
                Bs[buf][n][c4 + 1] = f2tf(pb[i].y);
                Bs[buf][n][c4 + 2] = f2tf(pb[i].z);
                Bs[buf][n][c4 + 3] = f2tf(pb[i].w);
            }
        } else {
#pragma unroll
            for (int i = 0; i < BNV; i++) {
                int idx = tid + i * 256;
                int kk = idx / (BN / 4), c4 = (idx % (BN / 4)) << 2;
                Bs[buf][c4 + 0][kk] = f2tf(pb[i].x);
                Bs[buf][c4 + 1][kk] = f2tf(pb[i].y);
                Bs[buf][c4 + 2][kk] = f2tf(pb[i].z);
                Bs[buf][c4 + 3][kk] = f2tf(pb[i].w);
            }
        }
    };

    float acc[MT][NT4][4] = {};

    gload(0);
    sstore(0);
    __syncthreads();

    int buf = 0;
    for (int ks = 0; ks < nk; ks++) {
        if (ks + 1 < nk) gload((ks + 1) * BK);
#pragma unroll
        for (int k8 = 0; k8 < 2; k8++) {
            unsigned af[MT][4], bf[NT4][2];
#pragma unroll
            for (int mt = 0; mt < MT; mt++) {
                int m = wr * WM + mt * 16;
                af[mt][0] = As[buf][m + g][k8 * 8 + t];
                af[mt][1] = As[buf][m + g + 8][k8 * 8 + t];
                af[mt][2] = As[buf][m + g][k8 * 8 + t + 4];
                af[mt][3] = As[buf][m + g + 8][k8 * 8 + t + 4];
            }
#pragma unroll
            for (int nt = 0; nt < NT4; nt++) {
                int n = wc * WN + nt * 8;
                bf[nt][0] = Bs[buf][n + g][k8 * 8 + t];
                bf[nt][1] = Bs[buf][n + g][k8 * 8 + t + 4];
            }
#pragma unroll
            for (int mt = 0; mt < MT; mt++)
#pragma unroll
                for (int nt = 0; nt < NT4; nt++)
                    mma_tf32(acc[mt][nt], af[mt], bf[nt]);
        }
        if (ks + 1 < nk) sstore(buf ^ 1);
        __syncthreads();
        buf ^= 1;
    }

#pragma unroll
    for (int mt = 0; mt < MT; mt++) {
#pragma unroll
        for (int nt = 0; nt < NT4; nt++) {
            int r0 = m0 + wr * WM + mt * 16 + g;
            int c0 = n0 + wc * WN + nt * 8 + 2 * t;
            float v0 = acc[mt][nt][0] * scale, v1 = acc[mt][nt][1] * scale;
            float v2 = acc[mt][nt][2] * scale, v3 = acc[mt][nt][3] * scale;
            if (BIAS) {
                float b0 = bias[c0], b1 = bias[c0 + 1];
                v0 += b0; v1 += b1; v2 += b0; v3 += b1;
            }
            if (RELU) {
                v0 = fmaxf(v0, 0.f); v1 = fmaxf(v1, 0.f);
                v2 = fmaxf(v2, 0.f); v3 = fmaxf(v3, 0.f);
            }
            float* p0 = C + (size_t)r0 * ldc + c0;
            float* p1 = C + (size_t)(r0 + 8) * ldc + c0;
            if (ACCUM) {
                float2 o0 = *(float2*)p0, o1 = *(float2*)p1;
                v0 += o0.x; v1 += o0.y; v2 += o1.x; v3 += o1.y;
            }
            *(float2*)p0 = make_float2(v0, v1);
            *(float2*)p1 = make_float2(v2, v3);
        }
    }
}

// ---------------- small kernels ----------------
__global__ void embed_kernel(const int* __restrict__ ids, const float* __restrict__ tok,
                             const float* __restrict__ pos, float* __restrict__ x) {
    int n = blockIdx.x, t = n % NT, id = ids[n];
    const float* te = tok + (size_t)id * ND;
    const float* pe = pos + (size_t)t * ND;
    float* dst = x + (size_t)n * ND;
    for (int d = threadIdx.x; d < ND; d += 256) dst[d] = te[d] + pe[d];
}

__global__ void ln_kernel(const float* __restrict__ x, const float* __restrict__ w,
                          const float* __restrict__ b, float* __restrict__ out) {
    int n = blockIdx.x, tid = threadIdx.x;
    const float* row = x + (size_t)n * ND;
    __shared__ float red[256];
    float s = 0.f;
    for (int d = tid; d < ND; d += 256) s += row[d];
    red[tid] = s; __syncthreads();
    for (int st = 128; st; st >>= 1) { if (tid < st) red[tid] += red[tid + st]; __syncthreads(); }
    float mu = red[0] * (1.0f / ND);
    __syncthreads();
    float v = 0.f;
    for (int d = tid; d < ND; d += 256) { float t = row[d] - mu; v += t * t; }
    red[tid] = v; __syncthreads();
    for (int st = 128; st; st >>= 1) { if (tid < st) red[tid] += red[tid + st]; __syncthreads(); }
    float rs = rsqrtf(red[0] * (1.0f / ND) + 1e-5f);
    float* dst = out + (size_t)n * ND;
    for (int d = tid; d < ND; d += 256) dst[d] = (row[d] - mu) * rs * w[d] + b[d];
}

__global__ void rope_kernel(float* __restrict__ qkv) {
    int nh = blockIdx.x;
    int n = nh >> 4, h = nh & 15;
    int t = n % NT, i = threadIdx.x;
    float ang = (float)t * expf((float)(2 * i) * (-0.14391156831212806f));
    float s = sinf(ang), c = cosf(ang);
    float* q = qkv + (size_t)n * 3072 + h * 64;
    float* k = q + 1024;
    float q1 = q[i], q2 = q[i + 32];
    q[i] = q1 * c - q2 * s; q[i + 32] = q2 * c + q1 * s;
    float k1 = k[i], k2 = k[i + 32];
    k[i] = k1 * c - k2 * s; k[i + 32] = k2 * c + k1 * s;
}

__global__ void attn_softmax_kernel(float* __restrict__ sc) {
    int r = blockIdx.x, tid = threadIdx.x;
    float* row = sc + (size_t)blockIdx.y * NT * NT + (size_t)r * NT;
    int n = r + 1;
    __shared__ float red[128];
    float m = -3.4e38f;
    for (int j = tid; j < n; j += 128) m = fmaxf(m, row[j]);
    red[tid] = m; __syncthreads();
    for (int s = 64; s; s >>= 1) { if (tid < s) red[tid] = fmaxf(red[tid], red[tid + s]); __syncthreads(); }
    m = red[0]; __syncthreads();
    float sum = 0.f;
    for (int j = tid; j < n; j += 128) { float e = expf(row[j] - m); row[j] = e; sum += e; }
    red[tid] = sum; __syncthreads();
    for (int s = 64; s; s >>= 1) { if (tid < s) red[tid] += red[tid + s]; __syncthreads(); }
    float inv = 1.0f / red[0];
    for (int j = tid; j < n; j += 128) row[j] *= inv;
    int rup = ((r >> 7) + 1) << 7;   // zero-pad to 128-tile boundary for PV
    for (int j = n + tid; j < rup; j += 128) row[j] = 0.f;
}

// ---------------- MoE ----------------
__global__ void route_kernel(const float* __restrict__ ln, const float* __restrict__ wr,
                             const float* __restrict__ br, const float* __restrict__ wn,
                             const float* __restrict__ bn, float* __restrict__ route,
                             float* __restrict__ noise) {
    int n = blockIdx.x, tid = threadIdx.x;
    __shared__ float xs[ND];
    for (int d = tid; d < ND; d += 256) xs[d] = ln[(size_t)n * ND + d];
    __syncthreads();
    int w = tid >> 5, lane = tid & 31;
    float sr = 0.f, sn = 0.f;
    for (int d = lane; d < ND; d += 32) {
        float xv = xs[d];
        sr += xv * wr[(size_t)d * NE + w];
        sn += xv * wn[(size_t)d * NE + w];
    }
    for (int o = 16; o; o >>= 1) { sr += __shfl_down_sync(~0u, sr, o); sn += __shfl_down_sync(~0u, sn, o); }
    if (!lane) { route[n * NE + w] = sr + br[w]; noise[n * NE + w] = sn + bn[w]; }
}

__global__ void eps_kernel(unsigned k0, unsigned k1, float* __restrict__ eps) {
    int i = blockIdx.x * 256 + threadIdx.x;
    if (i >= NN * NE) return;
    unsigned o0, o1;
    threefry(k0, k1, 0u, (unsigned)i, o0, o1);
    eps[i] = bits_to_normal(o0 ^ o1);
}

__global__ void topk_kernel(const float* __restrict__ route, const float* __restrict__ noise,
                            const float* __restrict__ eps, float* __restrict__ gate,
                            unsigned char* __restrict__ mask) {
    int n = blockIdx.x * 256 + threadIdx.x;
    if (n >= NN) return;
    float nv[NE];
#pragma unroll
    for (int e = 0; e < NE; e++) {
        float x = noise[n * NE + e];
        float sp = fmaxf(x, 0.f) + log1pf(expf(-fabsf(x)));
        nv[e] = route[n * NE + e] + eps[n * NE + e] * sp;
    }
    int i1 = 0; float v1 = nv[0];
#pragma unroll
    for (int e = 1; e < NE; e++) if (nv[e] > v1) { v1 = nv[e]; i1 = e; }
    int i2 = -1; float v2 = -3.4e38f;
#pragma unroll
    for (int e = 0; e < NE; e++) if (e != i1 && nv[e] > v2) { v2 = nv[e]; i2 = e; }
    float e2 = expf(v2 - v1);
    float Z = 1.0f + e2;
#pragma unroll
    for (int e = 0; e < NE; e++)
        gate[n * NE + e] = (e == i1) ? (1.0f / Z) : ((e == i2) ? (e2 / Z) : 0.f);
    mask[n] = (unsigned char)((1u << i1) | (1u << i2));
}

__global__ void select_kernel(const unsigned char* __restrict__ mask, int* __restrict__ sel,
                              int* __restrict__ slot, int* __restrict__ cnt) {
    int e = blockIdx.x, lane = threadIdx.x;
    int base = 0;
    for (int n0 = 0; n0 < NN; n0 += 32) {
        int n = n0 + lane;
        bool f = (mask[n] >> e) & 1;
        unsigned bal = __ballot_sync(0xffffffffu, f);
        int pos = base + __popc(bal & ((1u << lane) - 1u));
        int sl = (f && pos < NCAP) ? pos : -1;
        slot[(size_t)e * NN + n] = sl;
        if (sl >= 0) sel[e * NCAP + sl] = n;
        base += __popc(bal);
    }
    if (!lane) cnt[e] = base < NCAP ? base : NCAP;
}

__global__ void gather_kernel(const float* __restrict__ ln, const int* __restrict__ sel,
                              const int* __restrict__ cnt, float* __restrict__ xt) {
    int s = blockIdx.x;
    int e = s / NCAP, i = s % NCAP;
    float* dst = xt + (size_t)s * ND;
    if (i < cnt[e]) {
        const float* src = ln + (size_t)sel[s] * ND;
        for (int d = threadIdx.x; d < ND; d += 256) dst[d] = src[d];
    } else {
        for (int d = threadIdx.x; d < ND; d += 256) dst[d] = 0.f;
    }
}

__global__ void moe_scatter_kernel(const float* __restrict__ eo, const int* __restrict__ slot,
                                   const float* __restrict__ gate, float* __restrict__ x) {
    int n = blockIdx.x, tid = threadIdx.x;
    __shared__ int ss[NE];
    __shared__ float gg[NE];
    if (tid < NE) { ss[tid] = slot[(size_t)tid * NN + n]; gg[tid] = gate[n * NE + tid]; }
    __syncthreads();
    for (int d = tid; d < ND; d += 256) {
        float acc = 0.f;
#pragma unroll
        for (int e = 0; e < NE; e++) {
            int s = ss[e];
            if (s >= 0) acc += gg[e] * eo[((size_t)e * NCAP + s) * ND + d];
        }
        x[(size_t)n * ND + d] += acc;
    }
}

// ---------------- loss ----------------
__global__ void loss_kernel(const float* __restrict__ logits, const int* __restrict__ ids,
                            float* __restrict__ nll, float* __restrict__ vld) {
    int n = blockIdx.x, tid = threadIdx.x;
    int b = n / NT, t = n % NT;
    if (t == NT - 1) { if (!tid) { nll[n] = 0.f; vld[n] = 0.f; } return; }
    int tgt = ids[b * NT + t + 1];
    const float* row = logits + (size_t)n * NV;
    float m = -3.4e38f, s = 0.f;
    for (int j = tid; j < NV; j += 256) {
        float l = row[j];
        if (l > m) { s = s * expf(m - l) + 1.0f; m = l; }
        else s += expf(l - m);
    }
    __shared__ float sm[256], ssum[256];
    sm[tid] = m; ssum[tid] = s; __syncthreads();
    for (int st = 128; st; st >>= 1) {
        if (tid < st) {
            float m1 = sm[tid], s1 = ssum[tid], m2 = sm[tid + st], s2 = ssum[tid + st];
            float M = fmaxf(m1, m2);
            ssum[tid] = s1 * expf(m1 - M) + s2 * expf(m2 - M);
            sm[tid] = M;
        }
        __syncthreads();
    }
    if (!tid) {
        float lse = sm[0] + logf(ssum[0]);
        float v = (tgt != 2) ? 1.f : 0.f;
        nll[n] = -(row[tgt] - lse) * v;
        vld[n] = v;
    }
}

__global__ void reduce_kernel(const float* __restrict__ nll, const float* __restrict__ vld,
                              float* __restrict__ out) {
    __shared__ float s1[256], s2[256];
    int tid = threadIdx.x;
    float a = 0.f, b = 0.f;
    for (int i = tid; i < NN; i += 256) { a += nll[i]; b += vld[i]; }
    s1[tid] = a; s2[tid] = b; __syncthreads();
    for (int st = 128; st; st >>= 1) { if (tid < st) { s1[tid] += s1[tid + st]; s2[tid] += s2[tid + st]; } __syncthreads(); }
    if (!tid) out[0] = s1[0] / fmaxf(s2[0], 1.0f);
}

// ---------------- host launch ----------------
extern "C" void kernel_launch(void* const* d_in, const int* in_sizes, int n_in,
                              void* d_out, int out_size) {
    const int*   ids     = (const int*)d_in[0];
    const float* tok_emb = (const float*)d_in[1];
    const float* pos_emb = (const float*)d_in[2];
    const float* ln1_w   = (const float*)d_in[3];
    const float* ln1_b   = (const float*)d_in[4];
    const float* ln2_w   = (const float*)d_in[5];
    const float* ln2_b   = (const float*)d_in[6];
    const float* w_qkv   = (const float*)d_in[7];
    const float* w_out   = (const float*)d_in[8];
    const float* w_route = (const float*)d_in[9];
    const float* b_route = (const float*)d_in[10];
    const float* w_noise = (const float*)d_in[11];
    const float* b_noise = (const float*)d_in[12];
    const float* w_e1    = (const float*)d_in[13];
    const float* b_e1    = (const float*)d_in[14];
    const float* w_e2    = (const float*)d_in[15];
    const float* b_e2    = (const float*)d_in[16];
    const float* lnf_w   = (const float*)d_in[17];
    const float* lnf_b   = (const float*)d_in[18];
    float* out = (float*)d_out;

    float *x, *ln, *qkv, *attn, *sc, *route, *noise, *eps, *gate, *xt, *h1, *eo, *lg, *nll, *vld;
    unsigned char* mask; int *sel, *slot, *cnt;
    cudaGetSymbolAddress((void**)&x, g_x);       cudaGetSymbolAddress((void**)&ln, g_ln);
    cudaGetSymbolAddress((void**)&qkv, g_qkv);   cudaGetSymbolAddress((void**)&attn, g_attn);
    cudaGetSymbolAddress((void**)&sc, g_sc);     cudaGetSymbolAddress((void**)&route, g_route);
    cudaGetSymbolAddress((void**)&noise, g_noise); cudaGetSymbolAddress((void**)&eps, g_eps);
    cudaGetSymbolAddress((void**)&gate, g_gate); cudaGetSymbolAddress((void**)&mask, g_mask);
    cudaGetSymbolAddress((void**)&sel, g_sel);   cudaGetSymbolAddress((void**)&slot, g_slot);
    cudaGetSymbolAddress((void**)&cnt, g_cnt);   cudaGetSymbolAddress((void**)&xt, g_xt);
    cudaGetSymbolAddress((void**)&h1, g_h1);     cudaGetSymbolAddress((void**)&eo, g_eo);
    cudaGetSymbolAddress((void**)&lg, g_log);    cudaGetSymbolAddress((void**)&nll, g_nll);
    cudaGetSymbolAddress((void**)&vld, g_vld);

    embed_kernel<<<NN, 256>>>(ids, tok_emb, pos_emb, x);

    for (int l = 0; l < NLAY; l++) {
        // ---- attention block ----
        ln_kernel<<<NN, 256>>>(x, ln1_w + l * ND, ln1_b + l * ND, ln);
        // qkv = ln @ w_qkv : M=4096, N=3072, K=1024
        tc_gemm<128,128,2,4,false,false,false,false,false,false><<<dim3(24, 32, 1), 256>>>(
            ln, w_qkv + (size_t)l * ND * 3 * ND, nullptr, qkv,
            ND, ND, 3 * ND, 3 * ND, 1, 0, 0, 0, 0, 0, 0, 0, 1.0f);
        rope_kernel<<<NN * NH, 32>>>(qkv);
        // scores = Q @ K^T * 0.125 : per (b,h), M=N=2048, K=64, causal tiles
        tc_gemm<128,128,2,4,true,false,false,false,true,false><<<dim3(16, 16, NB * NH), 256>>>(
            qkv, qkv + 1024, nullptr, sc,
            64, 3072, 3072, NT, NH,
            (size_t)NT * 3072, 64, (size_t)NT * 3072, 64,
            (size_t)NH * NT * NT, (size_t)NT * NT, 0, 0.125f);
        attn_softmax_kernel<<<dim3(NT, NB * NH), 128>>>(sc);
        // attn = P @ V : per (b,h), M=2048, N=64, K limited per m-tile
        tc_gemm<128,64,4,2,false,false,false,false,false,true><<<dim3(1, 16, NB * NH), 256>>>(
            sc, qkv + 2048, nullptr, attn,
            NT, NT, 3072, ND, NH,
            (size_t)NH * NT * NT, (size_t)NT * NT, (size_t)NT * 3072, 64,
            (size_t)NT * ND, 64, 0, 1.0f);
        // x += attn @ w_out : M=4096, N=1024, K=1024
        tc_gemm<128,128,2,4,false,false,false,true,false,false><<<dim3(8, 32, 1), 256>>>(
            attn, w_out + (size_t)l * ND * ND, nullptr, x,
            ND, ND, ND, ND, 1, 0, 0, 0, 0, 0, 0, 0, 1.0f);

        // ---- MoE block ----
        ln_kernel<<<NN, 256>>>(x, ln2_w + l * ND, ln2_b + l * ND, ln);
        route_kernel<<<NN, 256>>>(ln, w_route + (size_t)l * ND * NE, b_route + l * NE,
                                  w_noise + (size_t)l * ND * NE, b_noise + l * NE, route, noise);
        unsigned k0, k1;
        threefry(0u, 1234u, 0u, (unsigned)l, k0, k1);
        eps_kernel<<<(NN * NE + 255) / 256, 256>>>(k0, k1, eps);
        topk_kernel<<<(NN + 255) / 256, 256>>>(route, noise, eps, gate, mask);
        select_kernel<<<NE, 32>>>(mask, sel, slot, cnt);
        gather_kernel<<<NE * NCAP, 256>>>(ln, sel, cnt, xt);
        // h1 = relu(xt @ w_e1 + b_e1) : z=8, M=1024, N=4096, K=1024
        tc_gemm<128,128,2,4,false,true,true,false,false,false><<<dim3(32, 8, NE), 256>>>(
            xt, w_e1 + (size_t)l * NE * ND * NFF, b_e1 + (size_t)l * NE * NFF, h1,
            ND, ND, NFF, NFF, 1,
            (size_t)NCAP * ND, 0, (size_t)ND * NFF, 0,
            (size_t)NCAP * NFF, 0, NFF, 1.0f);
        // eo = h1 @ w_e2 + b_e2 : z=8, M=1024, N=1024, K=4096
        tc_gemm<128,128,2,4,false,true,false,false,false,false><<<dim3(8, 8, NE), 256>>>(
            h1, w_e2 + (size_t)l * NE * NFF * ND, b_e2 + (size_t)l * NE * ND, eo,
            NFF, NFF, ND, ND, 1,
            (size_t)NCAP * NFF, 0, (size_t)NFF * ND, 0,
            (size_t)NCAP * ND, 0, ND, 1.0f);
        moe_scatter_kernel<<<NN, 256>>>(eo, slot, gate, x);
    }

    ln_kernel<<<NN, 256>>>(x, lnf_w, lnf_b, ln);
    // logits = ln @ tok_emb^T : M=4096, N=32000, K=1024 (B is [N,K])
    tc_gemm<128,128,2,4,true,false,false,false,false,false><<<dim3(NV / 128, 32, 1), 256>>>(
        ln, tok_emb, nullptr, lg,
        ND, ND, ND, NV, 1, 0, 0, 0, 0, 0, 0, 0, 1.0f);
    loss_kernel<<<NN, 256>>>(lg, ids, nll, vld);
    reduce_kernel<<<1, 256>>>(nll, vld, out);
}

// round 5
// speedup vs baseline: 2.2944x; 1.0651x over previous
#include <cuda_runtime.h>
#include <cstdint>
#include <cstddef>

#define NB 2
#define NT 2048
#define ND 1024
#define NH 16
#define NLAY 2
#define NE 8
#define NV 32000
#define NN (NB*NT)
#define NCAP 1024
#define NFF 4096

// ---------------- device scratch ----------------
__device__ float g_x   [(size_t)NN*ND];
__device__ float g_ln  [(size_t)NN*ND];
__device__ float g_qkv [(size_t)NN*3*ND];
__device__ float g_attn[(size_t)NN*ND];
__device__ float g_sc  [(size_t)NB*NH*NT*NT];
__device__ float g_route[NN*NE];
__device__ float g_noise[NN*NE];
__device__ float g_eps  [NN*NE];
__device__ float g_gate [NN*NE];
__device__ unsigned char g_mask[NN];
__device__ int   g_sel [NE*NCAP];
__device__ int   g_slot[NE*NN];
__device__ int   g_cnt [NE];
__device__ float g_xt  [(size_t)NE*NCAP*ND];
__device__ float g_h1  [(size_t)NE*NCAP*NFF];
__device__ float g_eo  [(size_t)NE*NCAP*ND];
__device__ float g_log [(size_t)NN*NV];
__device__ float g_nll [NN];
__device__ float g_vld [NN];

// ---------------- threefry2x32 (matches JAX) ----------------
__host__ __device__ __forceinline__ void threefry(unsigned k0, unsigned k1,
                                                  unsigned x0, unsigned x1,
                                                  unsigned& o0, unsigned& o1) {
    unsigned ks2 = k0 ^ k1 ^ 0x1BD11BDAu;
    x0 += k0; x1 += k1;
#define TFR(r) { x0 += x1; x1 = (x1 << (r)) | (x1 >> (32 - (r))); x1 ^= x0; }
    TFR(13) TFR(15) TFR(26) TFR(6)  x0 += k1;  x1 += ks2 + 1u;
    TFR(17) TFR(29) TFR(16) TFR(24) x0 += ks2; x1 += k0 + 2u;
    TFR(13) TFR(15) TFR(26) TFR(6)  x0 += k0;  x1 += k1 + 3u;
    TFR(17) TFR(29) TFR(16) TFR(24) x0 += k1;  x1 += ks2 + 4u;
    TFR(13) TFR(15) TFR(26) TFR(6)  x0 += ks2; x1 += k0 + 5u;
#undef TFR
    o0 = x0; o1 = x1;
}

// XLA ErfInv32 (Giles) polynomial
__device__ __forceinline__ float xla_erfinv(float x) {
    float w = -log1pf(-x * x);
    float p;
    if (w < 5.f) {
        w -= 2.5f;
        p = 2.81022636e-08f;
        p = fmaf(p, w, 3.43273939e-07f);
        p = fmaf(p, w, -3.5233877e-06f);
        p = fmaf(p, w, -4.39150654e-06f);
        p = fmaf(p, w, 0.00021858087f);
        p = fmaf(p, w, -0.00125372503f);
        p = fmaf(p, w, -0.00417768164f);
        p = fmaf(p, w, 0.246640727f);
        p = fmaf(p, w, 1.50140941f);
    } else {
        w = sqrtf(w) - 3.f;
        p = -0.000200214257f;
        p = fmaf(p, w, 0.000100950558f);
        p = fmaf(p, w, 0.00134934322f);
        p = fmaf(p, w, -0.00367342844f);
        p = fmaf(p, w, 0.00573950773f);
        p = fmaf(p, w, -0.0076224613f);
        p = fmaf(p, w, 0.00943887047f);
        p = fmaf(p, w, 1.00167406f);
        p = fmaf(p, w, 2.83297682f);
    }
    return p * x;
}

__device__ __forceinline__ float bits_to_normal(unsigned bits) {
    float f = __uint_as_float((bits >> 9) | 0x3F800000u) - 1.0f;
    const float lo = -0.99999994f;
    float u = fmaf(f, 2.0f, lo);
    u = fmaxf(u, lo);
    return 1.41421356237f * xla_erfinv(u);
}

// ---------------- tf32 mma helpers ----------------
__device__ __forceinline__ unsigned f2tf(float f) {
    unsigned u; asm("cvt.rna.tf32.f32 %0, %1;" : "=r"(u) : "f"(f)); return u;
}

__device__ __forceinline__ void mma_tf32(float* c, const unsigned* a, const unsigned* b) {
    asm volatile("mma.sync.aligned.m16n8k8.row.col.f32.tf32.tf32.f32 "
        "{%0,%1,%2,%3}, {%4,%5,%6,%7}, {%8,%9}, {%0,%1,%2,%3};"
        : "+f"(c[0]), "+f"(c[1]), "+f"(c[2]), "+f"(c[3])
        : "r"(a[0]), "r"(a[1]), "r"(a[2]), "r"(a[3]), "r"(b[0]), "r"(b[1]));
}

// ---------------- universal tf32 tensor-core GEMM ----------------
// C[M,N] = A[M,K] (row-major, lda) * B (BNK? [N,K] : [K,N], ldb)
// CAUSAL: skip tiles with n0 >= m0+BM. PVLIM: Keff = (by+1)*BM.
template<int TH, int BM, int BN, int WR, int WC, bool BNK, bool BIAS, bool RELU,
         bool ACCUM, bool CAUSAL, bool PVLIM>
__global__ void __launch_bounds__(TH)
tc_gemm(const float* __restrict__ A, const float* __restrict__ B,
        const float* __restrict__ bias, float* __restrict__ C,
        int K, int lda, int ldb, int ldc, int zdiv,
        size_t sA, size_t sA2, size_t sB, size_t sB2,
        size_t sC, size_t sC2, size_t sBias, float scale)
{
    constexpr int BK = 16;
    constexpr int WM = BM / WR, WN = BN / WC;
    constexpr int MT = WM / 16, NT4 = WN / 8;
    constexpr int ANV = (BM * BK) / (4 * TH);
    constexpr int BNV = (BN * BK) / (4 * TH);

    const int m0 = blockIdx.y * BM, n0 = blockIdx.x * BN;
    if (CAUSAL && n0 >= m0 + BM) return;

    const int tid = threadIdx.x, lane = tid & 31, warp = tid >> 5;
    const int wr = warp / WC, wc = warp % WC;
    const int g = lane >> 2, t = lane & 3;

    {
        int z = blockIdx.z, z1 = z / zdiv, z0 = z - z1 * zdiv;
        A += (size_t)z1 * sA + (size_t)z0 * sA2;
        B += (size_t)z1 * sB + (size_t)z0 * sB2;
        C += (size_t)z1 * sC + (size_t)z0 * sC2;
        if (BIAS) bias += (size_t)z1 * sBias;
    }

    int Keff = K;
    if (PVLIM) { int ke = ((int)blockIdx.y + 1) * BM; if (ke < Keff) Keff = ke; }
    const int nk = Keff / BK;

    extern __shared__ unsigned sh[];
    unsigned (*As)[20] = (unsigned(*)[20])sh;                 // [2*BM][20]
    unsigned (*Bs)[20] = (unsigned(*)[20])(sh + 2 * BM * 20); // [2*BN][20]

    float4 pa[ANV], pb[BNV];

    auto gload = [&](int k0) {
#pragma unroll
        for (int i = 0; i < ANV; i++) {
            int idx = tid + i * TH;
            int m = idx >> 2, c4 = (idx & 3) << 2;
            pa[i] = *(const float4*)(A + (size_t)(m0 + m) * lda + k0 + c4);
        }
        if (BNK) {
#pragma unroll
            for (int i = 0; i < BNV; i++) {
                int idx = tid + i * TH;
                int n = idx >> 2, c4 = (idx & 3) << 2;
                pb[i] = *(const float4*)(B + (size_t)(n0 + n) * ldb + k0 + c4);
            }
        } else {
#pragma unroll
            for (int i = 0; i < BNV; i++) {
                int idx = tid + i * TH;
                int kk = idx / (BN / 4), c4 = (idx % (BN / 4)) << 2;
                pb[i] = *(const float4*)(B + (size_t)(k0 + kk) * ldb + n0 + c4);
            }
        }
    };
    auto sstore = [&](int buf) {
#pragma unroll
        for (int i = 0; i < ANV; i++) {
            int idx = tid + i * TH;
            int m = idx >> 2, c4 = (idx & 3) << 2;
            unsigned* p = &As[buf * BM + m][c4];
            p[0] = f2tf(pa[i].x); p[1] = f2tf(pa[i].y);
            p[2] = f2tf(pa[i].z); p[3] = f2tf(pa[i].w);
        }
        if (BNK) {
#pragma unroll
            for (int i = 0; i < BNV; i++) {
                int idx = tid + i * TH;
                int n = idx >> 2, c4 = (idx & 3) << 2;
                unsigned* p = &Bs[buf * BN + n][c4];
                p[0] = f2tf(pb[i].x); p[1] = f2tf(pb[i].y);
                p[2] = f2tf(pb[i].z); p[3] = f2tf(pb[i].w);
            }
        } else {
#pragma unroll
            for (int i = 0; i < BNV; i++) {
                int idx = tid + i * TH;
                int kk = idx / (BN / 4), c4 = (idx % (BN / 4)) << 2;
                Bs[buf * BN + c4 + 0][kk] = f2tf(pb[i].x);
                Bs[buf * BN + c4 + 1][kk] = f2tf(pb[i].y);
                Bs[buf * BN + c4 + 2][kk] = f2tf(pb[i].z);
                Bs[buf * BN + c4 + 3][kk] = f2tf(pb[i].w);
            }
        }
    };

    float acc[MT][NT4][4] = {};

    gload(0);
    sstore(0);
    __syncthreads();

    int buf = 0;
    for (int ks = 0; ks < nk; ks++) {
        if (ks + 1 < nk) gload((ks + 1) * BK);
#pragma unroll
        for (int k8 = 0; k8 < 2; k8++) {
            unsigned af[MT][4], bf[NT4][2];
#pragma unroll
            for (int mt = 0; mt < MT; mt++) {
                int m = buf * BM + wr * WM + mt * 16;
                af[mt][0] = As[m + g][k8 * 8 + t];
                af[mt][1] = As[m + g + 8][k8 * 8 + t];
                af[mt][2] = As[m + g][k8 * 8 + t + 4];
                af[mt][3] = As[m + g + 8][k8 * 8 + t + 4];
            }
#pragma unroll
            for (int nt = 0; nt < NT4; nt++) {
                int n = buf * BN + wc * WN + nt * 8;
                bf[nt][0] = Bs[n + g][k8 * 8 + t];
                bf[nt][1] = Bs[n + g][k8 * 8 + t + 4];
            }
#pragma unroll
            for (int mt = 0; mt < MT; mt++)
#pragma unroll
                for (int nt = 0; nt < NT4; nt++)
                    mma_tf32(acc[mt][nt], af[mt], bf[nt]);
        }
        if (ks + 1 < nk) sstore(buf ^ 1);
        __syncthreads();
        buf ^= 1;
    }

#pragma unroll
    for (int mt = 0; mt < MT; mt++) {
#pragma unroll
        for (int nt = 0; nt < NT4; nt++) {
            int r0 = m0 + wr * WM + mt * 16 + g;
            int c0 = n0 + wc * WN + nt * 8 + 2 * t;
            float v0 = acc[mt][nt][0] * scale, v1 = acc[mt][nt][1] * scale;
            float v2 = acc[mt][nt][2] * scale, v3 = acc[mt][nt][3] * scale;
            if (BIAS) {
                float b0 = bias[c0], b1 = bias[c0 + 1];
                v0 += b0; v1 += b1; v2 += b0; v3 += b1;
            }
            if (RELU) {
                v0 = fmaxf(v0, 0.f); v1 = fmaxf(v1, 0.f);
                v2 = fmaxf(v2, 0.f); v3 = fmaxf(v3, 0.f);
            }
            float* p0 = C + (size_t)r0 * ldc + c0;
            float* p1 = C + (size_t)(r0 + 8) * ldc + c0;
            if (ACCUM) {
                float2 o0 = *(float2*)p0, o1 = *(float2*)p1;
                v0 += o0.x; v1 += o0.y; v2 += o1.x; v3 += o1.y;
            }
            *(float2*)p0 = make_float2(v0, v1);
            *(float2*)p1 = make_float2(v2, v3);
        }
    }
}

// ---------------- small kernels ----------------
__global__ void embed_kernel(const int* __restrict__ ids, const float* __restrict__ tok,
                             const float* __restrict__ pos, float* __restrict__ x) {
    int n = blockIdx.x, t = n % NT, id = ids[n];
    const float* te = tok + (size_t)id * ND;
    const float* pe = pos + (size_t)t * ND;
    float* dst = x + (size_t)n * ND;
    for (int d = threadIdx.x; d < ND; d += 256) dst[d] = te[d] + pe[d];
}

// warp-per-row LN: 8 rows per 256-thread block, single gmem read
__global__ void ln_kernel(const float* __restrict__ x, const float* __restrict__ w,
                          const float* __restrict__ b, float* __restrict__ out) {
    int row = blockIdx.x * 8 + (threadIdx.x >> 5);
    int lane = threadIdx.x & 31;
    const float4* p = (const float4*)(x + (size_t)row * ND);
    float4 v[8];
    float s = 0.f;
#pragma unroll
    for (int i = 0; i < 8; i++) {
        v[i] = p[lane + i * 32];
        s += v[i].x + v[i].y + v[i].z + v[i].w;
    }
#pragma unroll
    for (int o = 16; o; o >>= 1) s += __shfl_xor_sync(~0u, s, o);
    float mu = s * (1.0f / ND);
    float q = 0.f;
#pragma unroll
    for (int i = 0; i < 8; i++) {
        float a = v[i].x - mu, c = v[i].y - mu, d = v[i].z - mu, e = v[i].w - mu;
        q += a * a + c * c + d * d + e * e;
    }
#pragma unroll
    for (int o = 16; o; o >>= 1) q += __shfl_xor_sync(~0u, q, o);
    float rs = rsqrtf(q * (1.0f / ND) + 1e-5f);
    const float4* wp = (const float4*)w;
    const float4* bp = (const float4*)b;
    float4* op = (float4*)(out + (size_t)row * ND);
#pragma unroll
    for (int i = 0; i < 8; i++) {
        int j = lane + i * 32;
        float4 wv = wp[j], bv = bp[j], r;
        r.x = (v[i].x - mu) * rs * wv.x + bv.x;
        r.y = (v[i].y - mu) * rs * wv.y + bv.y;
        r.z = (v[i].z - mu) * rs * wv.z + bv.z;
        r.w = (v[i].w - mu) * rs * wv.w + bv.w;
        op[j] = r;
    }
}

__global__ void rope_kernel(float* __restrict__ qkv) {
    int n = blockIdx.x, t = n % NT;
    float* base = qkv + (size_t)n * 3072;
#pragma unroll
    for (int item = threadIdx.x; item < 512; item += 256) {
        int h = item >> 5, i = item & 31;
        float ang = (float)t * expf((float)(2 * i) * (-0.14391156831212806f));
        float s = sinf(ang), c = cosf(ang);
        float* q = base + h * 64;
        float* k = q + 1024;
        float q1 = q[i], q2 = q[i + 32];
        q[i] = q1 * c - q2 * s; q[i + 32] = q2 * c + q1 * s;
        float k1 = k[i], k2 = k[i + 32];
        k[i] = k1 * c - k2 * s; k[i + 32] = k2 * c + k1 * s;
    }
}

__global__ void attn_softmax_kernel(float* __restrict__ sc) {
    int r = blockIdx.x, tid = threadIdx.x;
    float* row = sc + (size_t)blockIdx.y * NT * NT + (size_t)r * NT;
    int n = r + 1;
    __shared__ float red[128];
    float m = -3.4e38f;
    for (int j = tid; j < n; j += 128) m = fmaxf(m, row[j]);
    red[tid] = m; __syncthreads();
    for (int s = 64; s; s >>= 1) { if (tid < s) red[tid] = fmaxf(red[tid], red[tid + s]); __syncthreads(); }
    m = red[0]; __syncthreads();
    float sum = 0.f;
    for (int j = tid; j < n; j += 128) { float e = expf(row[j] - m); row[j] = e; sum += e; }
    red[tid] = sum; __syncthreads();
    for (int s = 64; s; s >>= 1) { if (tid < s) red[tid] += red[tid + s]; __syncthreads(); }
    float inv = 1.0f / red[0];
    for (int j = tid; j < n; j += 128) row[j] *= inv;
    int rup = ((r >> 8) + 1) << 8;   // zero-pad to 256-tile boundary (QK tile extent)
    for (int j = n + tid; j < rup; j += 128) row[j] = 0.f;
}

// ---------------- MoE ----------------
__global__ void route_kernel(const float* __restrict__ ln, const float* __restrict__ wr,
                             const float* __restrict__ br, const float* __restrict__ wn,
                             const float* __restrict__ bn, float* __restrict__ route,
                             float* __restrict__ noise) {
    int n = blockIdx.x, tid = threadIdx.x;
    __shared__ float xs[ND];
    for (int d = tid; d < ND; d += 256) xs[d] = ln[(size_t)n * ND + d];
    __syncthreads();
    int w = tid >> 5, lane = tid & 31;
    float sr = 0.f, sn = 0.f;
    for (int d = lane; d < ND; d += 32) {
        float xv = xs[d];
        sr += xv * wr[(size_t)d * NE + w];
        sn += xv * wn[(size_t)d * NE + w];
    }
    for (int o = 16; o; o >>= 1) { sr += __shfl_down_sync(~0u, sr, o); sn += __shfl_down_sync(~0u, sn, o); }
    if (!lane) { route[n * NE + w] = sr + br[w]; noise[n * NE + w] = sn + bn[w]; }
}

__global__ void eps_kernel(unsigned k0, unsigned k1, float* __restrict__ eps) {
    int i = blockIdx.x * 256 + threadIdx.x;
    if (i >= NN * NE) return;
    unsigned o0, o1;
    threefry(k0, k1, 0u, (unsigned)i, o0, o1);
    eps[i] = bits_to_normal(o0 ^ o1);
}

__global__ void topk_kernel(const float* __restrict__ route, const float* __restrict__ noise,
                            const float* __restrict__ eps, float* __restrict__ gate,
                            unsigned char* __restrict__ mask) {
    int n = blockIdx.x * 256 + threadIdx.x;
    if (n >= NN) return;
    float nv[NE];
#pragma unroll
    for (int e = 0; e < NE; e++) {
        float x = noise[n * NE + e];
        float sp = fmaxf(x, 0.f) + log1pf(expf(-fabsf(x)));
        nv[e] = route[n * NE + e] + eps[n * NE + e] * sp;
    }
    int i1 = 0; float v1 = nv[0];
#pragma unroll
    for (int e = 1; e < NE; e++) if (nv[e] > v1) { v1 = nv[e]; i1 = e; }
    int i2 = -1; float v2 = -3.4e38f;
#pragma unroll
    for (int e = 0; e < NE; e++) if (e != i1 && nv[e] > v2) { v2 = nv[e]; i2 = e; }
    float e2 = expf(v2 - v1);
    float Z = 1.0f + e2;
#pragma unroll
    for (int e = 0; e < NE; e++)
        gate[n * NE + e] = (e == i1) ? (1.0f / Z) : ((e == i2) ? (e2 / Z) : 0.f);
    mask[n] = (unsigned char)((1u << i1) | (1u << i2));
}

__global__ void select_kernel(const unsigned char* __restrict__ mask, int* __restrict__ sel,
                              int* __restrict__ slot, int* __restrict__ cnt) {
    int e = blockIdx.x, lane = threadIdx.x;
    int base = 0;
    for (int n0 = 0; n0 < NN; n0 += 32) {
        int n = n0 + lane;
        bool f = (mask[n] >> e) & 1;
        unsigned bal = __ballot_sync(0xffffffffu, f);
        int pos = base + __popc(bal & ((1u << lane) - 1u));
        int sl = (f && pos < NCAP) ? pos : -1;
        slot[(size_t)e * NN + n] = sl;
        if (sl >= 0) sel[e * NCAP + sl] = n;
        base += __popc(bal);
    }
    if (!lane) cnt[e] = base < NCAP ? base : NCAP;
}

__global__ void gather_kernel(const float* __restrict__ ln, const int* __restrict__ sel,
                              const int* __restrict__ cnt, float* __restrict__ xt) {
    int s = blockIdx.x;
    int e = s / NCAP, i = s % NCAP;
    float* dst = xt + (size_t)s * ND;
    if (i < cnt[e]) {
        const float* src = ln + (size_t)sel[s] * ND;
        for (int d = threadIdx.x; d < ND; d += 256) dst[d] = src[d];
    } else {
        for (int d = threadIdx.x; d < ND; d += 256) dst[d] = 0.f;
    }
}

__global__ void moe_scatter_kernel(const float* __restrict__ eo, const int* __restrict__ slot,
                                   const float* __restrict__ gate, float* __restrict__ x) {
    int n = blockIdx.x, tid = threadIdx.x;
    __shared__ int ss[NE];
    __shared__ float gg[NE];
    if (tid < NE) { ss[tid] = slot[(size_t)tid * NN + n]; gg[tid] = gate[n * NE + tid]; }
    __syncthreads();
    for (int d = tid; d < ND; d += 256) {
        float acc = 0.f;
#pragma unroll
        for (int e = 0; e < NE; e++) {
            int s = ss[e];
            if (s >= 0) acc += gg[e] * eo[((size_t)e * NCAP + s) * ND + d];
        }
        x[(size_t)n * ND + d] += acc;
    }
}

// ---------------- loss ----------------
__global__ void loss_kernel(const float* __restrict__ logits, const int* __restrict__ ids,
                            float* __restrict__ nll, float* __restrict__ vld) {
    int n = blockIdx.x, tid = threadIdx.x;
    int b = n / NT, t = n % NT;
    if (t == NT - 1) { if (!tid) { nll[n] = 0.f; vld[n] = 0.f; } return; }
    int tgt = ids[b * NT + t + 1];
    const float* row = logits + (size_t)n * NV;
    float m = -3.4e38f, s = 0.f;
    for (int j = tid; j < NV; j += 256) {
        float l = row[j];
        if (l > m) { s = s * expf(m - l) + 1.0f; m = l; }
        else s += expf(l - m);
    }
    __shared__ float sm[256], ssum[256];
    sm[tid] = m; ssum[tid] = s; __syncthreads();
    for (int st = 128; st; st >>= 1) {
        if (tid < st) {
            float m1 = sm[tid], s1 = ssum[tid], m2 = sm[tid + st], s2 = ssum[tid + st];
            float M = fmaxf(m1, m2);
            ssum[tid] = s1 * expf(m1 - M) + s2 * expf(m2 - M);
            sm[tid] = M;
        }
        __syncthreads();
    }
    if (!tid) {
        float lse = sm[0] + logf(ssum[0]);
        float v = (tgt != 2) ? 1.f : 0.f;
        nll[n] = -(row[tgt] - lse) * v;
        vld[n] = v;
    }
}

__global__ void reduce_kernel(const float* __restrict__ nll, const float* __restrict__ vld,
                              float* __restrict__ out) {
    __shared__ float s1[256], s2[256];
    int tid = threadIdx.x;
    float a = 0.f, b = 0.f;
    for (int i = tid; i < NN; i += 256) { a += nll[i]; b += vld[i]; }
    s1[tid] = a; s2[tid] = b; __syncthreads();
    for (int st = 128; st; st >>= 1) { if (tid < st) { s1[tid] += s1[tid + st]; s2[tid] += s2[tid + st]; } __syncthreads(); }
    if (!tid) out[0] = s1[0] / fmaxf(s2[0], 1.0f);
}

// ---------------- host launch ----------------
#define SMEM_BYTES(BM, BN) ((2*(BM)*20 + 2*(BN)*20) * 4)

extern "C" void kernel_launch(void* const* d_in, const int* in_sizes, int n_in,
                              void* d_out, int out_size) {
    const int*   ids     = (const int*)d_in[0];
    const float* tok_emb = (const float*)d_in[1];
    const float* pos_emb = (const float*)d_in[2];
    const float* ln1_w   = (const float*)d_in[3];
    const float* ln1_b   = (const float*)d_in[4];
    const float* ln2_w   = (const float*)d_in[5];
    const float* ln2_b   = (const float*)d_in[6];
    const float* w_qkv   = (const float*)d_in[7];
    const float* w_out   = (const float*)d_in[8];
    const float* w_route = (const float*)d_in[9];
    const float* b_route = (const float*)d_in[10];
    const float* w_noise = (const float*)d_in[11];
    const float* b_noise = (const float*)d_in[12];
    const float* w_e1    = (const float*)d_in[13];
    const float* b_e1    = (const float*)d_in[14];
    const float* w_e2    = (const float*)d_in[15];
    const float* b_e2    = (const float*)d_in[16];
    const float* lnf_w   = (const float*)d_in[17];
    const float* lnf_b   = (const float*)d_in[18];
    float* out = (float*)d_out;

    float *x, *ln, *qkv, *attn, *sc, *route, *noise, *eps, *gate, *xt, *h1, *eo, *lg, *nll, *vld;
    unsigned char* mask; int *sel, *slot, *cnt;
    cudaGetSymbolAddress((void**)&x, g_x);       cudaGetSymbolAddress((void**)&ln, g_ln);
    cudaGetSymbolAddress((void**)&qkv, g_qkv);   cudaGetSymbolAddress((void**)&attn, g_attn);
    cudaGetSymbolAddress((void**)&sc, g_sc);     cudaGetSymbolAddress((void**)&route, g_route);
    cudaGetSymbolAddress((void**)&noise, g_noise); cudaGetSymbolAddress((void**)&eps, g_eps);
    cudaGetSymbolAddress((void**)&gate, g_gate); cudaGetSymbolAddress((void**)&mask, g_mask);
    cudaGetSymbolAddress((void**)&sel, g_sel);   cudaGetSymbolAddress((void**)&slot, g_slot);
    cudaGetSymbolAddress((void**)&cnt, g_cnt);   cudaGetSymbolAddress((void**)&xt, g_xt);
    cudaGetSymbolAddress((void**)&h1, g_h1);     cudaGetSymbolAddress((void**)&eo, g_eo);
    cudaGetSymbolAddress((void**)&lg, g_log);    cudaGetSymbolAddress((void**)&nll, g_nll);
    cudaGetSymbolAddress((void**)&vld, g_vld);

    // big-tile instantiations need >48KB dynamic smem
    constexpr int BIG_SMEM = SMEM_BYTES(256, 128);
    constexpr int MED_SMEM = SMEM_BYTES(128, 128);
    constexpr int PV_SMEM  = SMEM_BYTES(128, 64);
    auto* kqkv   = tc_gemm<512,256,128,4,4,false,false,false,false,false,false>;
    auto* kqk    = tc_gemm<512,256,128,4,4,true, false,false,false,true, false>;
    auto* kpv    = tc_gemm<256,128, 64,4,2,false,false,false,false,false,true >;
    auto* kproj  = tc_gemm<256,128,128,2,4,false,false,false,true, false,false>;
    auto* kfc1   = tc_gemm<512,256,128,4,4,false,true, true, false,false,false>;
    auto* kfc2   = tc_gemm<256,128,128,2,4,false,true, false,false,false,false>;
    auto* kvocab = tc_gemm<512,256,128,4,4,true, false,false,false,false,false>;
    cudaFuncSetAttribute(kqkv,   cudaFuncAttributeMaxDynamicSharedMemorySize, BIG_SMEM);
    cudaFuncSetAttribute(kqk,    cudaFuncAttributeMaxDynamicSharedMemorySize, BIG_SMEM);
    cudaFuncSetAttribute(kfc1,   cudaFuncAttributeMaxDynamicSharedMemorySize, BIG_SMEM);
    cudaFuncSetAttribute(kvocab, cudaFuncAttributeMaxDynamicSharedMemorySize, BIG_SMEM);

    embed_kernel<<<NN, 256>>>(ids, tok_emb, pos_emb, x);

    for (int l = 0; l < NLAY; l++) {
        // ---- attention block ----
        ln_kernel<<<NN / 8, 256>>>(x, ln1_w + l * ND, ln1_b + l * ND, ln);
        // qkv = ln @ w_qkv : M=4096, N=3072, K=1024
        kqkv<<<dim3(24, 16, 1), 512, BIG_SMEM>>>(
            ln, w_qkv + (size_t)l * ND * 3 * ND, nullptr, qkv,
            ND, ND, 3 * ND, 3 * ND, 1, 0, 0, 0, 0, 0, 0, 0, 1.0f);
        rope_kernel<<<NN, 256>>>(qkv);
        // scores = Q @ K^T * 0.125 : per (b,h), M=N=2048, K=64, causal tiles
        kqk<<<dim3(16, 8, NB * NH), 512, BIG_SMEM>>>(
            qkv, qkv + 1024, nullptr, sc,
            64, 3072, 3072, NT, NH,
            (size_t)NT * 3072, 64, (size_t)NT * 3072, 64,
            (size_t)NH * NT * NT, (size_t)NT * NT, 0, 0.125f);
        attn_softmax_kernel<<<dim3(NT, NB * NH), 128>>>(sc);
        // attn = P @ V : per (b,h), M=2048, N=64, K limited per m-tile
        kpv<<<dim3(1, 16, NB * NH), 256, PV_SMEM>>>(
            sc, qkv + 2048, nullptr, attn,
            NT, NT, 3072, ND, NH,
            (size_t)NH * NT * NT, (size_t)NT * NT, (size_t)NT * 3072, 64,
            (size_t)NT * ND, 64, 0, 1.0f);
        // x += attn @ w_out : M=4096, N=1024, K=1024
        kproj<<<dim3(8, 32, 1), 256, MED_SMEM>>>(
            attn, w_out + (size_t)l * ND * ND, nullptr, x,
            ND, ND, ND, ND, 1, 0, 0, 0, 0, 0, 0, 0, 1.0f);

        // ---- MoE block ----
        ln_kernel<<<NN / 8, 256>>>(x, ln2_w + l * ND, ln2_b + l * ND, ln);
        route_kernel<<<NN, 256>>>(ln, w_route + (size_t)l * ND * NE, b_route + l * NE,
                                  w_noise + (size_t)l * ND * NE, b_noise + l * NE, route, noise);
        unsigned k0, k1;
        threefry(0u, 1234u, 0u, (unsigned)l, k0, k1);
        eps_kernel<<<(NN * NE + 255) / 256, 256>>>(k0, k1, eps);
        topk_kernel<<<(NN + 255) / 256, 256>>>(route, noise, eps, gate, mask);
        select_kernel<<<NE, 32>>>(mask, sel, slot, cnt);
        gather_kernel<<<NE * NCAP, 256>>>(ln, sel, cnt, xt);
        // h1 = relu(xt @ w_e1 + b_e1) : z=8, M=1024, N=4096, K=1024
        kfc1<<<dim3(32, 4, NE), 512, BIG_SMEM>>>(
            xt, w_e1 + (size_t)l * NE * ND * NFF, b_e1 + (size_t)l * NE * NFF, h1,
            ND, ND, NFF, NFF, 1,
            (size_t)NCAP * ND, 0, (size_t)ND * NFF, 0,
            (size_t)NCAP * NFF, 0, NFF, 1.0f);
        // eo = h1 @ w_e2 + b_e2 : z=8, M=1024, N=1024, K=4096
        kfc2<<<dim3(8, 8, NE), 256, MED_SMEM>>>(
            h1, w_e2 + (size_t)l * NE * NFF * ND, b_e2 + (size_t)l * NE * ND, eo,
            NFF, NFF, ND, ND, 1,
            (size_t)NCAP * NFF, 0, (size_t)NFF * ND, 0,
            (size_t)NCAP * ND, 0, ND, 1.0f);
        moe_scatter_kernel<<<NN, 256>>>(eo, slot, gate, x);
    }

    ln_kernel<<<NN / 8, 256>>>(x, lnf_w, lnf_b, ln);
    // logits = ln @ tok_emb^T : M=4096, N=32000, K=1024 (B is [N,K])
    kvocab<<<dim3(NV / 128, 16, 1), 512, BIG_SMEM>>>(
        ln, tok_emb, nullptr, lg,
        ND, ND, ND, NV, 1, 0, 0, 0, 0, 0, 0, 0, 1.0f);
    loss_kernel<<<NN, 256>>>(lg, ids, nll, vld);
    reduce_kernel<<<1, 256>>>(nll, vld, out);
}